// round 14
// baseline (speedup 1.0000x reference)
#include <cuda_runtime.h>
#include <cuda_fp16.h>
#include <cstdint>

#define N_GENES 16384
#define N_REG   8192
#define D_MODEL 256
#define OUT_DIM 128
#define ALPHA   0.2f

#define TI 64
#define TJ 64
#define NTJ 256
#define N_ITILES (N_REG / TI)
#define NJOBS (N_ITILES * NTJ)
#define NQUADS (NJOBS / 4)
#define GRID_ATTN 304

#define SM_P    0
#define SMEM_BYTES 16384       // 2 x 8 KB P double buffer only
#define SMEM_G1 65536          // gemm1h: 2 stages x (16KB A + 16KB B)

// ---------------- device scratch ----------------
__device__ __align__(16) __half g_inph[N_GENES * D_MODEL];  // inp fp16
__device__ __align__(16) __half g_Wh  [D_MODEL * OUT_DIM];  // W fp16
__device__ __align__(16) __half g_whh [N_GENES * OUT_DIM];  // w_h fp16
__device__ __align__(16) uint2  g_V2  [NTJ * 4 * 16 * 32];  // V in B-fragment layout (4 MB)
__device__ float  g_wh1[N_REG];
__device__ float  g_wh2[N_GENES];
__device__ float  g_F1 [N_GENES];
__device__ float  g_F2 [N_GENES];
__device__ float  g_G1 [N_REG];
__device__ float  g_G2 [N_REG];
__device__ unsigned g_w2max_bits;
__device__ float  g_D  [(size_t)N_REG * OUT_DIM];
__device__ float  g_S  [N_REG];

// ---------------- helpers ----------------
static __device__ __forceinline__ uint32_t swz(uint32_t x) { return x ^ ((x >> 3) & 0x70); }
static __device__ __forceinline__ uint32_t smem_u32(const void* p) {
    return (uint32_t)__cvta_generic_to_shared(p);
}
static __device__ __forceinline__ unsigned fenc(float f) {
    unsigned u = __float_as_uint(f);
    return (u & 0x80000000u) ? ~u : (u | 0x80000000u);
}
static __device__ __forceinline__ float fdec(unsigned k) {
    unsigned u = (k & 0x80000000u) ? (k ^ 0x80000000u) : ~k;
    return __uint_as_float(u);
}

// ---------------- K1: prep — fp16 conversions + zero D/S ----------------
__global__ void k_prep(const float* __restrict__ inp, const float* __restrict__ W) {
    const int t = blockIdx.x * 256 + threadIdx.x;    // 0 .. 1048575
    if (t == 0) g_w2max_bits = 0u;
    {
        float4 v = *(const float4*)&inp[(size_t)t * 4];
        __half2 h0 = __floats2half2_rn(v.x, v.y);
        __half2 h1 = __floats2half2_rn(v.z, v.w);
        uint2 u; u.x = *(uint32_t*)&h0; u.y = *(uint32_t*)&h1;
        *(uint2*)&g_inph[(size_t)t * 4] = u;
    }
    if (t < (D_MODEL * OUT_DIM) / 4) {
        float4 v = *(const float4*)&W[t * 4];
        __half2 h0 = __floats2half2_rn(v.x, v.y);
        __half2 h1 = __floats2half2_rn(v.z, v.w);
        uint2 u; u.x = *(uint32_t*)&h0; u.y = *(uint32_t*)&h1;
        *(uint2*)&g_Wh[t * 4] = u;
    }
    if (t < ((size_t)N_REG * OUT_DIM) / 4)
        ((float4*)g_D)[t] = make_float4(0.f, 0.f, 0.f, 0.f);
    if (t < N_REG) g_S[t] = 0.f;
}

// ---------------- K2: w_h = inp @ W via HMMA (+fused wh1/wh2/max) ----------------
__global__ void __launch_bounds__(256, 1)
k_gemm1h(const float* __restrict__ a) {
    extern __shared__ char smem[];
    const uint32_t sb = smem_u32(smem);
    float* sP1 = (float*)(smem);
    float* sP2 = (float*)(smem + 1024);

    const int t    = threadIdx.x;
    const int lane = t & 31, warp = t >> 5;
    const int wi   = warp >> 1, wc = warp & 1;
    const int r0   = blockIdx.x * 128;

    auto load_chunk = [&](int kc, int st) {
        const uint32_t AB = sb + st * 32768;
        const uint32_t BB = AB + 16384;
        #pragma unroll
        for (int u = 0; u < 4; u++) {
            const int idx = t + u * 256;
            {
                const int row = idx >> 3, ch = idx & 7;
                const __half* src = &g_inph[(size_t)(r0 + row) * D_MODEL + kc * 64 + ch * 8];
                asm volatile("cp.async.cg.shared.global [%0], [%1], 16;"
                             :: "r"(AB + swz(row * 128 + ch * 16)), "l"(src));
            }
            {
                const int row = idx >> 4, seg = idx & 15;
                const __half* src = &g_Wh[(kc * 64 + row) * OUT_DIM + seg * 8];
                const uint32_t dst = BB + (seg >> 3) * 8192 + swz(row * 128 + (seg & 7) * 16);
                asm volatile("cp.async.cg.shared.global [%0], [%1], 16;" :: "r"(dst), "l"(src));
            }
        }
        asm volatile("cp.async.commit_group;" ::: "memory");
    };

    float d[2][8][4];
    #pragma unroll
    for (int ah = 0; ah < 2; ah++)
        #pragma unroll
        for (int n = 0; n < 8; n++)
            #pragma unroll
            for (int k = 0; k < 4; k++) d[ah][n][k] = 0.f;

    load_chunk(0, 0);
    #pragma unroll
    for (int kc = 0; kc < 4; kc++) {
        if (kc + 1 < 4) load_chunk(kc + 1, (kc + 1) & 1);
        if (kc + 1 < 4) asm volatile("cp.async.wait_group 1;" ::: "memory");
        else            asm volatile("cp.async.wait_group 0;" ::: "memory");
        __syncthreads();

        const uint32_t AB = sb + (kc & 1) * 32768;
        const uint32_t BB = AB + 16384;
        #pragma unroll
        for (int ks = 0; ks < 4; ks++) {
            uint32_t afr[2][4];
            #pragma unroll
            for (int ah = 0; ah < 2; ah++) {
                const uint32_t aaddr = AB + swz((wi * 32 + ah * 16 + (lane & 15)) * 128
                                                + ks * 32 + (lane >> 4) * 16);
                asm volatile("ldmatrix.sync.aligned.m8n8.x4.shared.b16 {%0,%1,%2,%3},[%4];\n"
                             : "=r"(afr[ah][0]), "=r"(afr[ah][1]),
                               "=r"(afr[ah][2]), "=r"(afr[ah][3]) : "r"(aaddr));
            }
            uint32_t bfr[4][4];
            #pragma unroll
            for (int nb = 0; nb < 4; nb++) {
                const int cin = nb * 16 + (lane >> 4) * 8;
                const uint32_t baddr = BB + wc * 8192
                                     + swz((ks * 16 + (lane & 15)) * 128 + cin * 2);
                asm volatile("ldmatrix.sync.aligned.m8n8.x4.trans.shared.b16 {%0,%1,%2,%3},[%4];\n"
                             : "=r"(bfr[nb][0]), "=r"(bfr[nb][1]),
                               "=r"(bfr[nb][2]), "=r"(bfr[nb][3]) : "r"(baddr));
            }
            #pragma unroll
            for (int ah = 0; ah < 2; ah++)
                #pragma unroll
                for (int n = 0; n < 8; n++) {
                    asm volatile(
                        "mma.sync.aligned.m16n8k16.row.col.f32.f16.f16.f32 "
                        "{%0,%1,%2,%3},{%4,%5,%6,%7},{%8,%9},{%0,%1,%2,%3};\n"
                        : "+f"(d[ah][n][0]), "+f"(d[ah][n][1]),
                          "+f"(d[ah][n][2]), "+f"(d[ah][n][3])
                        : "r"(afr[ah][0]), "r"(afr[ah][1]), "r"(afr[ah][2]), "r"(afr[ah][3]),
                          "r"(bfr[n >> 1][(n & 1) * 2]), "r"(bfr[n >> 1][(n & 1) * 2 + 1]));
                }
        }
        __syncthreads();
    }

    float s1[2][2] = {{0.f,0.f},{0.f,0.f}}, s2[2][2] = {{0.f,0.f},{0.f,0.f}};
    #pragma unroll
    for (int ah = 0; ah < 2; ah++) {
        const int r1 = wi * 32 + ah * 16 + (lane >> 2);
        #pragma unroll
        for (int n = 0; n < 8; n++) {
            const int c = wc * 64 + n * 8 + (lane & 3) * 2;
            __half2 h0 = __floats2half2_rn(d[ah][n][0], d[ah][n][1]);
            __half2 h1 = __floats2half2_rn(d[ah][n][2], d[ah][n][3]);
            *(uint32_t*)&g_whh[(size_t)(r0 + r1) * OUT_DIM + c]     = *(uint32_t*)&h0;
            *(uint32_t*)&g_whh[(size_t)(r0 + r1 + 8) * OUT_DIM + c] = *(uint32_t*)&h1;
            const float a10 = a[c], a11 = a[c + 1];
            const float a20 = a[OUT_DIM + c], a21 = a[OUT_DIM + c + 1];
            s1[ah][0] += d[ah][n][0] * a10 + d[ah][n][1] * a11;
            s2[ah][0] += d[ah][n][0] * a20 + d[ah][n][1] * a21;
            s1[ah][1] += d[ah][n][2] * a10 + d[ah][n][3] * a11;
            s2[ah][1] += d[ah][n][2] * a20 + d[ah][n][3] * a21;
        }
    }
    __syncthreads();
    #pragma unroll
    for (int ah = 0; ah < 2; ah++)
        #pragma unroll
        for (int h = 0; h < 2; h++) {
            float v1 = s1[ah][h], v2 = s2[ah][h];
            v1 += __shfl_xor_sync(0xffffffffu, v1, 1);
            v1 += __shfl_xor_sync(0xffffffffu, v1, 2);
            v2 += __shfl_xor_sync(0xffffffffu, v2, 1);
            v2 += __shfl_xor_sync(0xffffffffu, v2, 2);
            if ((lane & 3) == 0) {
                const int row = wi * 32 + ah * 16 + h * 8 + (lane >> 2);
                sP1[wc * 128 + row] = v1;
                sP2[wc * 128 + row] = v2;
            }
        }
    __syncthreads();
    __shared__ float smax[4];
    if (t < 128) {
        const float v1 = sP1[t] + sP1[128 + t];
        const float v2 = sP2[t] + sP2[128 + t];
        if (r0 + t < N_REG) g_wh1[r0 + t] = v1;
        g_wh2[r0 + t] = v2;
        float m = v2;
        #pragma unroll
        for (int o = 16; o; o >>= 1) m = fmaxf(m, __shfl_xor_sync(0xffffffffu, m, o));
        if ((t & 31) == 0) smax[t >> 5] = m;
    }
    __syncthreads();
    if (t == 0) {
        float m = fmaxf(fmaxf(smax[0], smax[1]), fmaxf(smax[2], smax[3]));
        atomicMax(&g_w2max_bits, fenc(m));
    }
}

// ---------------- K3: exp factor tables + V -> B-fragment permute ----------------
// grid 1024 blocks x 128 threads; block B0 = (J, ks) handles 16 j-rows.
__global__ void k_factperm() {
    __shared__ __half sv[16][128];
    const int B0 = blockIdx.x;           // 0..1023
    const int t  = threadIdx.x;          // 0..127
    const int J  = B0 >> 2, ks = B0 & 3;
    const int jbase = B0 * 16;           // == J*64 + ks*16

    #pragma unroll
    for (int u = 0; u < 2; u++) {
        const int idx = t + u * 128;     // 256 uint4
        const int row = idx >> 4, seg = idx & 15;
        *(uint4*)&sv[row][seg * 8] =
            *(const uint4*)&g_whh[(size_t)(jbase + row) * OUT_DIM + seg * 8];
    }
    if (t < 16) {
        const int j = jbase + t;
        const float w2m = fdec(g_w2max_bits);
        float w2 = g_wh2[j];
        g_F1[j] = expf(w2);
        g_F2[j] = expf(ALPHA * w2);
        if (j < N_REG) {
            float w1 = g_wh1[j];
            float x  = w1 + w2m;
            float B  = x > 0.f ? x : ALPHA * x;
            g_G1[j] = expf(w1 - B);
            g_G2[j] = expf(ALPHA * w1 - B);
        }
    }
    __syncthreads();
    #pragma unroll
    for (int g = 0; g < 4; g++) {
        const int nb = g * 4 + (t >> 5), lane = t & 31;
        const int j0 = (lane & 3) * 2, c = nb * 8 + (lane >> 2);
        __half2 w0 = __halves2half2(sv[j0][c],     sv[j0 + 1][c]);
        __half2 w1 = __halves2half2(sv[j0 + 8][c], sv[j0 + 9][c]);
        uint2 o; o.x = *(uint32_t*)&w0; o.y = *(uint32_t*)&w1;
        g_V2[(size_t)J * 2048 + ks * 512 + nb * 32 + lane] = o;
    }
}

// ---------------- K4: persistent fused masked-softmax attention (V via fragment LDG) ----
__global__ void __launch_bounds__(256, 2)
k_attn(const float* __restrict__ adj) {
    extern __shared__ char smem[];
    const uint32_t sb = smem_u32(smem);

    const int t    = threadIdx.x;
    const int lane = t & 31, warp = t >> 5;
    const int rh   = lane >> 4;
    const int q    = lane & 15;
    const int wi   = warp >> 2, wc = warp & 3;

    const int s = 4 * (int)(((long long)blockIdx.x * NQUADS) / GRID_ATTN);
    const int e = 4 * (int)(((long long)(blockIdx.x + 1) * NQUADS) / GRID_ATTN);

    float4 av[4], f1q, f2q;
    auto prefetch = [&](int m) {
        if (m < e) {
            const int jo = (m & (NTJ - 1)) * TJ;
            const float* base = adj + ((size_t)(m >> 8) * TI + warp * 8 + rh * 4) * N_GENES
                              + jo + q * 4;
            #pragma unroll
            for (int r = 0; r < 4; r++)
                av[r] = __ldg((const float4*)(base + (size_t)r * N_GENES));
            f1q = *(const float4*)&g_F1[jo + q * 4];
            f2q = *(const float4*)&g_F2[jo + q * 4];
        }
    };

    float G1r[4], G2r[4], sacc[4];
    float d[2][4][4];
    uint32_t dh[2][4][2];

    auto load_row_consts = [&](int it) {
        #pragma unroll
        for (int r = 0; r < 4; r++) {
            const int i = it * TI + warp * 8 + rh * 4 + r;
            G1r[r] = g_G1[i];
            G2r[r] = g_G2[i];
            sacc[r] = 0.f;
        }
    };
    auto reset_D = [&]() {
        #pragma unroll
        for (int ah = 0; ah < 2; ah++)
            #pragma unroll
            for (int n = 0; n < 4; n++) {
                d[ah][n][0] = d[ah][n][1] = d[ah][n][2] = d[ah][n][3] = 0.f;
                dh[ah][n][0] = dh[ah][n][1] = 0u;
            }
    };
    auto fold = [&]() {
        #pragma unroll
        for (int ah = 0; ah < 2; ah++)
            #pragma unroll
            for (int n = 0; n < 4; n++) {
                float2 lo = __half22float2(*(__half2*)&dh[ah][n][0]);
                float2 hi = __half22float2(*(__half2*)&dh[ah][n][1]);
                d[ah][n][0] += lo.x; d[ah][n][1] += lo.y;
                d[ah][n][2] += hi.x; d[ah][n][3] += hi.y;
                dh[ah][n][0] = 0u;   dh[ah][n][1] = 0u;
            }
    };
    auto flush_S = [&](int it) {
        #pragma unroll
        for (int r = 0; r < 4; r++) {
            float v = sacc[r];
            v += __shfl_xor_sync(0xffffffffu, v, 8);
            v += __shfl_xor_sync(0xffffffffu, v, 4);
            v += __shfl_xor_sync(0xffffffffu, v, 2);
            v += __shfl_xor_sync(0xffffffffu, v, 1);
            if (q == 0) atomicAdd(&g_S[it * TI + warp * 8 + rh * 4 + r], v);
        }
    };
    auto flush_D = [&](int it) {
        fold();
        #pragma unroll
        for (int ah = 0; ah < 2; ah++) {
            const int r1 = wi * 32 + ah * 16 + (lane >> 2);
            #pragma unroll
            for (int n = 0; n < 4; n++) {
                const int c = wc * 32 + n * 8 + (lane & 3) * 2;
                float* p0 = &g_D[(size_t)(it * TI + r1) * OUT_DIM + c];
                float* p1 = &g_D[(size_t)(it * TI + r1 + 8) * OUT_DIM + c];
                atomicAdd(p0,     d[ah][n][0]);
                atomicAdd(p0 + 1, d[ah][n][1]);
                atomicAdd(p1,     d[ah][n][2]);
                atomicAdd(p1 + 1, d[ah][n][3]);
                d[ah][n][0] = d[ah][n][1] = d[ah][n][2] = d[ah][n][3] = 0.f;
            }
        }
    };
    auto build_P = [&](int m, uint32_t PB) {
        #pragma unroll
        for (int r = 0; r < 4; r++) {
            const float G1 = G1r[r], G2 = G2r[r];
            float p0 = av[r].x * fmaxf(G1 * f1q.x, G2 * f2q.x);
            float p1 = av[r].y * fmaxf(G1 * f1q.y, G2 * f2q.y);
            float p2 = av[r].z * fmaxf(G1 * f1q.z, G2 * f2q.z);
            float p3 = av[r].w * fmaxf(G1 * f1q.w, G2 * f2q.w);
            sacc[r] += (p0 + p1) + (p2 + p3);
            __half2 h01 = __floats2half2_rn(p0, p1);
            __half2 h23 = __floats2half2_rn(p2, p3);
            asm volatile("st.shared.v2.b32 [%0], {%1, %2};"
                         :: "r"(PB + swz((warp * 8 + rh * 4 + r) * 128 + q * 8)),
                            "r"(*(uint32_t*)&h01), "r"(*(uint32_t*)&h23));
        }
    };

    // ---- prologue ----
    prefetch(s);
    int it_b = s >> 8;
    load_row_consts(it_b);
    reset_D();
    build_P(s, sb + SM_P);
    prefetch(s + 1);

    // ---- main loop: one barrier per tile; build P[m+1] overlaps MMA[m] ----
    for (int mb = s; mb < e; mb += 2) {
        #pragma unroll
        for (int u = 0; u < 2; u++) {
            const int m = mb + u;
            const uint32_t PB = sb + SM_P + u * 8192;            // P[m] (m&1 == u)

            __syncthreads();   // P[m] visible; MMA m-1 done -> PB[(m+1)&1] free

            if (m + 1 < e) {
                if (u == 1) {                     // (m+1)%256==0 only possible when m odd
                    const int it_n = (m + 1) >> 8;
                    if (it_n != it_b) {
                        flush_S(it_b);
                        it_b = it_n;
                        load_row_consts(it_b);
                    }
                }
                build_P(m + 1, sb + SM_P + ((u + 1) & 1) * 8192);
                prefetch(m + 2);
            }

            // ---- MMA: D(32x32 per warp) += P(32x64) @ V(64x32); B frags via LDG ----
            const uint2* vb = g_V2 + (size_t)(m & (NTJ - 1)) * 2048 + wc * 128 + lane;
            uint2 bc[4];
            #pragma unroll
            for (int n = 0; n < 4; n++) bc[n] = __ldg(&vb[n * 32]);

            #pragma unroll
            for (int ks = 0; ks < 4; ks++) {
                uint2 bn[4];
                if (ks < 3) {
                    #pragma unroll
                    for (int n = 0; n < 4; n++) bn[n] = __ldg(&vb[(ks + 1) * 512 + n * 32]);
                }
                uint32_t afr[2][4];
                #pragma unroll
                for (int ah = 0; ah < 2; ah++) {
                    const uint32_t aaddr = PB + swz((wi * 32 + ah * 16 + (lane & 15)) * 128
                                                    + ks * 32 + (lane >> 4) * 16);
                    asm volatile("ldmatrix.sync.aligned.m8n8.x4.shared.b16 {%0,%1,%2,%3},[%4];\n"
                                 : "=r"(afr[ah][0]), "=r"(afr[ah][1]),
                                   "=r"(afr[ah][2]), "=r"(afr[ah][3]) : "r"(aaddr));
                }
                #pragma unroll
                for (int ah = 0; ah < 2; ah++)
                    #pragma unroll
                    for (int n = 0; n < 4; n++) {
                        asm volatile(
                            "mma.sync.aligned.m16n8k16.row.col.f16.f16.f16.f16 "
                            "{%0,%1},{%2,%3,%4,%5},{%6,%7},{%0,%1};\n"
                            : "+r"(dh[ah][n][0]), "+r"(dh[ah][n][1])
                            : "r"(afr[ah][0]), "r"(afr[ah][1]), "r"(afr[ah][2]), "r"(afr[ah][3]),
                              "r"(bc[n].x), "r"(bc[n].y));
                    }
                if (ks < 3) {
                    #pragma unroll
                    for (int n = 0; n < 4; n++) bc[n] = bn[n];
                }
            }

            if (u == 1) {   // flush at i-tile/range end, else fold (2-tile cadence)
                if (m + 1 == e || ((m + 1) & (NTJ - 1)) == 0) {
                    flush_D(m >> 8);
                } else {
                    fold();
                }
            }
        }
    }
    flush_S(it_b);
}

// ---------------- K5: normalize + ELU ----------------
__global__ void k_combine(float* __restrict__ out) {
    const int i = blockIdx.x, c = threadIdx.x;
    const float s = g_S[i];
    const size_t idx = (size_t)i * OUT_DIM + c;
    float v = g_D[idx] / s;
    out[idx] = v > 0.f ? v : expm1f(v);
}

// ---------------- launch ----------------
extern "C" void kernel_launch(void* const* d_in, const int* in_sizes, int n_in,
                              void* d_out, int out_size) {
    const float* inp = (const float*)d_in[0];   // [16384, 256]
    const float* adj = (const float*)d_in[1];   // [8192, 16384]
    const float* W   = (const float*)d_in[2];   // [256, 128]
    const float* a   = (const float*)d_in[3];   // [256, 1]
    float* out = (float*)d_out;                 // [8192, 128]

    cudaFuncSetAttribute(k_attn,   cudaFuncAttributeMaxDynamicSharedMemorySize, SMEM_BYTES);
    cudaFuncSetAttribute(k_gemm1h, cudaFuncAttributeMaxDynamicSharedMemorySize, SMEM_G1);

    k_prep    <<<(N_GENES * D_MODEL / 4) / 256, 256>>>(inp, W);   // launch 1
    k_gemm1h  <<<N_GENES / 128, 256, SMEM_G1>>>(a);               // launch 2
    k_factperm<<<NTJ * 4, 128>>>();                               // launch 3
    k_attn    <<<GRID_ATTN, 256, SMEM_BYTES>>>(adj);              // launch 4 (ncu target)
    k_combine <<<N_REG, OUT_DIM>>>(out);                          // launch 5
}

// round 15
// speedup vs baseline: 1.3227x; 1.3227x over previous
#include <cuda_runtime.h>
#include <cuda_fp16.h>
#include <cstdint>

#define N_GENES 16384
#define N_REG   8192
#define D_MODEL 256
#define OUT_DIM 128
#define ALPHA   0.2f

#define TI 64
#define TJ 64
#define NTJ 256
#define N_ITILES (N_REG / TI)
#define NJOBS (N_ITILES * NTJ)
#define NQUADS (NJOBS / 4)
#define GRID_ATTN 304

#define SM_P    0
#define SM_V    16384
#define SMEM_BYTES 81920
#define SMEM_G1 65536          // gemm1h: 2 stages x (16KB A + 16KB B)

// ---------------- device scratch ----------------
__device__ __align__(16) __half g_inph[N_GENES * D_MODEL];  // inp fp16
__device__ __align__(16) __half g_Wh  [D_MODEL * OUT_DIM];  // W fp16
__device__ __align__(16) __half g_whh [N_GENES * OUT_DIM];  // w_h fp16
__device__ float  g_wh1[N_REG];
__device__ float  g_wh2[N_GENES];
__device__ float  g_F1 [N_GENES];
__device__ float  g_F2 [N_GENES];
__device__ float  g_G1 [N_REG];
__device__ float  g_G2 [N_REG];
__device__ unsigned g_w2max_bits;
__device__ float  g_D  [(size_t)N_REG * OUT_DIM];
__device__ float  g_S  [N_REG];

// ---------------- helpers ----------------
static __device__ __forceinline__ uint32_t swz(uint32_t x) { return x ^ ((x >> 3) & 0x70); }
static __device__ __forceinline__ uint32_t smem_u32(const void* p) {
    return (uint32_t)__cvta_generic_to_shared(p);
}
static __device__ __forceinline__ unsigned fenc(float f) {
    unsigned u = __float_as_uint(f);
    return (u & 0x80000000u) ? ~u : (u | 0x80000000u);
}
static __device__ __forceinline__ float fdec(unsigned k) {
    unsigned u = (k & 0x80000000u) ? (k ^ 0x80000000u) : ~k;
    return __uint_as_float(u);
}

// ---------------- K1: prep — fp16 conversions + zero D/S ----------------
__global__ void k_prep(const float* __restrict__ inp, const float* __restrict__ W) {
    const int t = blockIdx.x * 256 + threadIdx.x;    // 0 .. 1048575
    if (t == 0) g_w2max_bits = 0u;
    {
        float4 v = *(const float4*)&inp[(size_t)t * 4];
        __half2 h0 = __floats2half2_rn(v.x, v.y);
        __half2 h1 = __floats2half2_rn(v.z, v.w);
        uint2 u; u.x = *(uint32_t*)&h0; u.y = *(uint32_t*)&h1;
        *(uint2*)&g_inph[(size_t)t * 4] = u;
    }
    if (t < (D_MODEL * OUT_DIM) / 4) {
        float4 v = *(const float4*)&W[t * 4];
        __half2 h0 = __floats2half2_rn(v.x, v.y);
        __half2 h1 = __floats2half2_rn(v.z, v.w);
        uint2 u; u.x = *(uint32_t*)&h0; u.y = *(uint32_t*)&h1;
        *(uint2*)&g_Wh[t * 4] = u;
    }
    if (t < ((size_t)N_REG * OUT_DIM) / 4)
        ((float4*)g_D)[t] = make_float4(0.f, 0.f, 0.f, 0.f);
    if (t < N_REG) g_S[t] = 0.f;
}

// ---------------- K2: w_h = inp @ W via HMMA (+fused wh1/wh2/max + F1/F2) ----------------
__global__ void __launch_bounds__(256, 1)
k_gemm1h(const float* __restrict__ a) {
    extern __shared__ char smem[];
    const uint32_t sb = smem_u32(smem);
    float* sP1 = (float*)(smem);
    float* sP2 = (float*)(smem + 1024);

    const int t    = threadIdx.x;
    const int lane = t & 31, warp = t >> 5;
    const int wi   = warp >> 1, wc = warp & 1;
    const int r0   = blockIdx.x * 128;

    auto load_chunk = [&](int kc, int st) {
        const uint32_t AB = sb + st * 32768;
        const uint32_t BB = AB + 16384;
        #pragma unroll
        for (int u = 0; u < 4; u++) {
            const int idx = t + u * 256;
            {
                const int row = idx >> 3, ch = idx & 7;
                const __half* src = &g_inph[(size_t)(r0 + row) * D_MODEL + kc * 64 + ch * 8];
                asm volatile("cp.async.cg.shared.global [%0], [%1], 16;"
                             :: "r"(AB + swz(row * 128 + ch * 16)), "l"(src));
            }
            {
                const int row = idx >> 4, seg = idx & 15;
                const __half* src = &g_Wh[(kc * 64 + row) * OUT_DIM + seg * 8];
                const uint32_t dst = BB + (seg >> 3) * 8192 + swz(row * 128 + (seg & 7) * 16);
                asm volatile("cp.async.cg.shared.global [%0], [%1], 16;" :: "r"(dst), "l"(src));
            }
        }
        asm volatile("cp.async.commit_group;" ::: "memory");
    };

    float d[2][8][4];
    #pragma unroll
    for (int ah = 0; ah < 2; ah++)
        #pragma unroll
        for (int n = 0; n < 8; n++)
            #pragma unroll
            for (int k = 0; k < 4; k++) d[ah][n][k] = 0.f;

    load_chunk(0, 0);
    #pragma unroll
    for (int kc = 0; kc < 4; kc++) {
        if (kc + 1 < 4) load_chunk(kc + 1, (kc + 1) & 1);
        if (kc + 1 < 4) asm volatile("cp.async.wait_group 1;" ::: "memory");
        else            asm volatile("cp.async.wait_group 0;" ::: "memory");
        __syncthreads();

        const uint32_t AB = sb + (kc & 1) * 32768;
        const uint32_t BB = AB + 16384;
        #pragma unroll
        for (int ks = 0; ks < 4; ks++) {
            uint32_t afr[2][4];
            #pragma unroll
            for (int ah = 0; ah < 2; ah++) {
                const uint32_t aaddr = AB + swz((wi * 32 + ah * 16 + (lane & 15)) * 128
                                                + ks * 32 + (lane >> 4) * 16);
                asm volatile("ldmatrix.sync.aligned.m8n8.x4.shared.b16 {%0,%1,%2,%3},[%4];\n"
                             : "=r"(afr[ah][0]), "=r"(afr[ah][1]),
                               "=r"(afr[ah][2]), "=r"(afr[ah][3]) : "r"(aaddr));
            }
            uint32_t bfr[4][4];
            #pragma unroll
            for (int nb = 0; nb < 4; nb++) {
                const int cin = nb * 16 + (lane >> 4) * 8;
                const uint32_t baddr = BB + wc * 8192
                                     + swz((ks * 16 + (lane & 15)) * 128 + cin * 2);
                asm volatile("ldmatrix.sync.aligned.m8n8.x4.trans.shared.b16 {%0,%1,%2,%3},[%4];\n"
                             : "=r"(bfr[nb][0]), "=r"(bfr[nb][1]),
                               "=r"(bfr[nb][2]), "=r"(bfr[nb][3]) : "r"(baddr));
            }
            #pragma unroll
            for (int ah = 0; ah < 2; ah++)
                #pragma unroll
                for (int n = 0; n < 8; n++) {
                    asm volatile(
                        "mma.sync.aligned.m16n8k16.row.col.f32.f16.f16.f32 "
                        "{%0,%1,%2,%3},{%4,%5,%6,%7},{%8,%9},{%0,%1,%2,%3};\n"
                        : "+f"(d[ah][n][0]), "+f"(d[ah][n][1]),
                          "+f"(d[ah][n][2]), "+f"(d[ah][n][3])
                        : "r"(afr[ah][0]), "r"(afr[ah][1]), "r"(afr[ah][2]), "r"(afr[ah][3]),
                          "r"(bfr[n >> 1][(n & 1) * 2]), "r"(bfr[n >> 1][(n & 1) * 2 + 1]));
                }
        }
        __syncthreads();
    }

    float s1[2][2] = {{0.f,0.f},{0.f,0.f}}, s2[2][2] = {{0.f,0.f},{0.f,0.f}};
    #pragma unroll
    for (int ah = 0; ah < 2; ah++) {
        const int r1 = wi * 32 + ah * 16 + (lane >> 2);
        #pragma unroll
        for (int n = 0; n < 8; n++) {
            const int c = wc * 64 + n * 8 + (lane & 3) * 2;
            __half2 h0 = __floats2half2_rn(d[ah][n][0], d[ah][n][1]);
            __half2 h1 = __floats2half2_rn(d[ah][n][2], d[ah][n][3]);
            *(uint32_t*)&g_whh[(size_t)(r0 + r1) * OUT_DIM + c]     = *(uint32_t*)&h0;
            *(uint32_t*)&g_whh[(size_t)(r0 + r1 + 8) * OUT_DIM + c] = *(uint32_t*)&h1;
            const float a10 = a[c], a11 = a[c + 1];
            const float a20 = a[OUT_DIM + c], a21 = a[OUT_DIM + c + 1];
            s1[ah][0] += d[ah][n][0] * a10 + d[ah][n][1] * a11;
            s2[ah][0] += d[ah][n][0] * a20 + d[ah][n][1] * a21;
            s1[ah][1] += d[ah][n][2] * a10 + d[ah][n][3] * a11;
            s2[ah][1] += d[ah][n][2] * a20 + d[ah][n][3] * a21;
        }
    }
    __syncthreads();
    #pragma unroll
    for (int ah = 0; ah < 2; ah++)
        #pragma unroll
        for (int h = 0; h < 2; h++) {
            float v1 = s1[ah][h], v2 = s2[ah][h];
            v1 += __shfl_xor_sync(0xffffffffu, v1, 1);
            v1 += __shfl_xor_sync(0xffffffffu, v1, 2);
            v2 += __shfl_xor_sync(0xffffffffu, v2, 1);
            v2 += __shfl_xor_sync(0xffffffffu, v2, 2);
            if ((lane & 3) == 0) {
                const int row = wi * 32 + ah * 16 + h * 8 + (lane >> 2);
                sP1[wc * 128 + row] = v1;
                sP2[wc * 128 + row] = v2;
            }
        }
    __syncthreads();
    __shared__ float smax[4];
    if (t < 128) {
        const float v1 = sP1[t] + sP1[128 + t];
        const float v2 = sP2[t] + sP2[128 + t];
        if (r0 + t < N_REG) g_wh1[r0 + t] = v1;
        g_wh2[r0 + t] = v2;
        g_F1[r0 + t] = expf(v2);              // F tables need no global max
        g_F2[r0 + t] = expf(ALPHA * v2);
        float m = v2;
        #pragma unroll
        for (int o = 16; o; o >>= 1) m = fmaxf(m, __shfl_xor_sync(0xffffffffu, m, o));
        if ((t & 31) == 0) smax[t >> 5] = m;
    }
    __syncthreads();
    if (t == 0) {
        float m = fmaxf(fmaxf(smax[0], smax[1]), fmaxf(smax[2], smax[3]));
        atomicMax(&g_w2max_bits, fenc(m));
    }
}

// ---------------- K3: G1/G2 tables (needs global max) ----------------
__global__ void k_factG() {
    const int j = blockIdx.x * 256 + threadIdx.x;     // 0..8191
    const float w2m = fdec(g_w2max_bits);
    float w1 = g_wh1[j];
    float x  = w1 + w2m;
    float B  = x > 0.f ? x : ALPHA * x;
    g_G1[j] = expf(w1 - B);
    g_G2[j] = expf(ALPHA * w1 - B);
}

// ---------------- K4: persistent fused masked-softmax attention (proven R12/13 body) -----
__global__ void __launch_bounds__(256, 2)
k_attn(const float* __restrict__ adj) {
    extern __shared__ char smem[];
    const uint32_t sb = smem_u32(smem);

    const int t    = threadIdx.x;
    const int lane = t & 31, warp = t >> 5;
    const int rh   = lane >> 4;
    const int q    = lane & 15;
    const int wi   = warp >> 2, wc = warp & 3;

    const int s = 4 * (int)(((long long)blockIdx.x * NQUADS) / GRID_ATTN);
    const int e = 4 * (int)(((long long)(blockIdx.x + 1) * NQUADS) / GRID_ATTN);

    auto load_stage = [&](int m, int slot) {
        if (m < e) {
            const uint32_t VB = sb + SM_V + slot * 16384;
            const int jo = (m & (NTJ - 1)) * TJ;
            #pragma unroll
            for (int u = 0; u < 4; u++) {
                const int idx = t + u * 256;
                const int row = idx >> 4, seg = idx & 15;
                const __half* src = &g_whh[(size_t)(jo + row) * OUT_DIM + seg * 8];
                const uint32_t dst = VB + (seg >> 3) * 8192 + swz(row * 128 + (seg & 7) * 16);
                asm volatile("cp.async.cg.shared.global [%0], [%1], 16;" :: "r"(dst), "l"(src));
            }
        }
        asm volatile("cp.async.commit_group;" ::: "memory");
    };

    float4 av[4], f1q, f2q;
    auto prefetch = [&](int m) {
        if (m < e) {
            const int jo = (m & (NTJ - 1)) * TJ;
            const float* base = adj + ((size_t)(m >> 8) * TI + warp * 8 + rh * 4) * N_GENES
                              + jo + q * 4;
            #pragma unroll
            for (int r = 0; r < 4; r++)
                av[r] = __ldg((const float4*)(base + (size_t)r * N_GENES));
            f1q = *(const float4*)&g_F1[jo + q * 4];
            f2q = *(const float4*)&g_F2[jo + q * 4];
        }
    };

    float G1r[4], G2r[4], sacc[4];
    float d[2][4][4];
    uint32_t dh[2][4][2];

    auto load_row_consts = [&](int it) {
        #pragma unroll
        for (int r = 0; r < 4; r++) {
            const int i = it * TI + warp * 8 + rh * 4 + r;
            G1r[r] = g_G1[i];
            G2r[r] = g_G2[i];
            sacc[r] = 0.f;
        }
    };
    auto reset_D = [&]() {
        #pragma unroll
        for (int ah = 0; ah < 2; ah++)
            #pragma unroll
            for (int n = 0; n < 4; n++) {
                d[ah][n][0] = d[ah][n][1] = d[ah][n][2] = d[ah][n][3] = 0.f;
                dh[ah][n][0] = dh[ah][n][1] = 0u;
            }
    };
    auto fold = [&]() {
        #pragma unroll
        for (int ah = 0; ah < 2; ah++)
            #pragma unroll
            for (int n = 0; n < 4; n++) {
                float2 lo = __half22float2(*(__half2*)&dh[ah][n][0]);
                float2 hi = __half22float2(*(__half2*)&dh[ah][n][1]);
                d[ah][n][0] += lo.x; d[ah][n][1] += lo.y;
                d[ah][n][2] += hi.x; d[ah][n][3] += hi.y;
                dh[ah][n][0] = 0u;   dh[ah][n][1] = 0u;
            }
    };
    auto flush_S = [&](int it) {
        #pragma unroll
        for (int r = 0; r < 4; r++) {
            float v = sacc[r];
            v += __shfl_xor_sync(0xffffffffu, v, 8);
            v += __shfl_xor_sync(0xffffffffu, v, 4);
            v += __shfl_xor_sync(0xffffffffu, v, 2);
            v += __shfl_xor_sync(0xffffffffu, v, 1);
            if (q == 0) atomicAdd(&g_S[it * TI + warp * 8 + rh * 4 + r], v);
        }
    };
    auto flush_D = [&](int it) {
        fold();
        #pragma unroll
        for (int ah = 0; ah < 2; ah++) {
            const int r1 = wi * 32 + ah * 16 + (lane >> 2);
            #pragma unroll
            for (int n = 0; n < 4; n++) {
                const int c = wc * 32 + n * 8 + (lane & 3) * 2;
                float* p0 = &g_D[(size_t)(it * TI + r1) * OUT_DIM + c];
                float* p1 = &g_D[(size_t)(it * TI + r1 + 8) * OUT_DIM + c];
                atomicAdd(p0,     d[ah][n][0]);
                atomicAdd(p0 + 1, d[ah][n][1]);
                atomicAdd(p1,     d[ah][n][2]);
                atomicAdd(p1 + 1, d[ah][n][3]);
                d[ah][n][0] = d[ah][n][1] = d[ah][n][2] = d[ah][n][3] = 0.f;
            }
        }
    };
    auto build_P = [&](int m, uint32_t PB) {
        #pragma unroll
        for (int r = 0; r < 4; r++) {
            const float G1 = G1r[r], G2 = G2r[r];
            float p0 = av[r].x * fmaxf(G1 * f1q.x, G2 * f2q.x);
            float p1 = av[r].y * fmaxf(G1 * f1q.y, G2 * f2q.y);
            float p2 = av[r].z * fmaxf(G1 * f1q.z, G2 * f2q.z);
            float p3 = av[r].w * fmaxf(G1 * f1q.w, G2 * f2q.w);
            sacc[r] += (p0 + p1) + (p2 + p3);
            __half2 h01 = __floats2half2_rn(p0, p1);
            __half2 h23 = __floats2half2_rn(p2, p3);
            asm volatile("st.shared.v2.b32 [%0], {%1, %2};"
                         :: "r"(PB + swz((warp * 8 + rh * 4 + r) * 128 + q * 8)),
                            "r"(*(uint32_t*)&h01), "r"(*(uint32_t*)&h23));
        }
    };

    prefetch(s);
    load_stage(s, 0);
    load_stage(s + 1, 1);
    load_stage(s + 2, 2);
    int it_b = s >> 8;
    load_row_consts(it_b);
    reset_D();
    build_P(s, sb + SM_P);
    prefetch(s + 1);

    for (int mb = s; mb < e; mb += 4) {
        #pragma unroll
        for (int u = 0; u < 4; u++) {
            const int m = mb + u;
            const uint32_t PB = sb + SM_P + (u & 1) * 8192;
            const uint32_t VB = sb + SM_V + u * 16384;

            asm volatile("cp.async.wait_group 2;" ::: "memory");
            __syncthreads();

            load_stage(m + 3, (u + 3) & 3);

            if (m + 1 < e) {
                if (u == 3) {
                    const int it_n = (m + 1) >> 8;
                    if (it_n != it_b) {
                        flush_S(it_b);
                        it_b = it_n;
                        load_row_consts(it_b);
                    }
                }
                build_P(m + 1, sb + SM_P + ((u + 1) & 1) * 8192);
                prefetch(m + 2);
            }

            #pragma unroll
            for (int ks = 0; ks < 4; ks++) {
                uint32_t afr[2][4];
                #pragma unroll
                for (int ah = 0; ah < 2; ah++) {
                    const uint32_t aaddr = PB + swz((wi * 32 + ah * 16 + (lane & 15)) * 128
                                                    + ks * 32 + (lane >> 4) * 16);
                    asm volatile("ldmatrix.sync.aligned.m8n8.x4.shared.b16 {%0,%1,%2,%3},[%4];\n"
                                 : "=r"(afr[ah][0]), "=r"(afr[ah][1]),
                                   "=r"(afr[ah][2]), "=r"(afr[ah][3]) : "r"(aaddr));
                }
                uint32_t bfr[8];
                const int atom = wc >> 1;
                const int cin0 = (wc & 1) * 32 + (lane >> 4) * 8;
                const uint32_t brow = (ks * 16 + (lane & 15)) * 128;
                const uint32_t baddr0 = VB + atom * 8192 + swz(brow + cin0 * 2);
                asm volatile("ldmatrix.sync.aligned.m8n8.x4.trans.shared.b16 {%0,%1,%2,%3},[%4];\n"
                             : "=r"(bfr[0]), "=r"(bfr[1]), "=r"(bfr[2]), "=r"(bfr[3]) : "r"(baddr0));
                const uint32_t baddr1 = VB + atom * 8192 + swz(brow + (cin0 + 16) * 2);
                asm volatile("ldmatrix.sync.aligned.m8n8.x4.trans.shared.b16 {%0,%1,%2,%3},[%4];\n"
                             : "=r"(bfr[4]), "=r"(bfr[5]), "=r"(bfr[6]), "=r"(bfr[7]) : "r"(baddr1));
                #pragma unroll
                for (int ah = 0; ah < 2; ah++)
                    #pragma unroll
                    for (int n = 0; n < 4; n++) {
                        asm volatile(
                            "mma.sync.aligned.m16n8k16.row.col.f16.f16.f16.f16 "
                            "{%0,%1},{%2,%3,%4,%5},{%6,%7},{%0,%1};\n"
                            : "+r"(dh[ah][n][0]), "+r"(dh[ah][n][1])
                            : "r"(afr[ah][0]), "r"(afr[ah][1]), "r"(afr[ah][2]), "r"(afr[ah][3]),
                              "r"(bfr[n * 2]), "r"(bfr[n * 2 + 1]));
                    }
            }

            if (u == 3) {
                if (m + 1 == e || ((m + 1) & (NTJ - 1)) == 0) {
                    flush_D(m >> 8);
                } else {
                    fold();
                }
            }
        }
    }
    flush_S(it_b);
}

// ---------------- K5: normalize + ELU (float4) ----------------
__global__ void k_combine(float* __restrict__ out) {
    const int idx = blockIdx.x * 256 + threadIdx.x;   // 0..262143, one float4 each
    const int row = idx >> 5, c4 = idx & 31;
    const float inv = 1.0f / g_S[row];
    float4 v = *(const float4*)&g_D[(size_t)row * OUT_DIM + c4 * 4];
    v.x *= inv; v.y *= inv; v.z *= inv; v.w *= inv;
    float4 o;
    o.x = v.x > 0.f ? v.x : expm1f(v.x);
    o.y = v.y > 0.f ? v.y : expm1f(v.y);
    o.z = v.z > 0.f ? v.z : expm1f(v.z);
    o.w = v.w > 0.f ? v.w : expm1f(v.w);
    *(float4*)&out[(size_t)row * OUT_DIM + c4 * 4] = o;
}

// ---------------- launch ----------------
extern "C" void kernel_launch(void* const* d_in, const int* in_sizes, int n_in,
                              void* d_out, int out_size) {
    const float* inp = (const float*)d_in[0];   // [16384, 256]
    const float* adj = (const float*)d_in[1];   // [8192, 16384]
    const float* W   = (const float*)d_in[2];   // [256, 128]
    const float* a   = (const float*)d_in[3];   // [256, 1]
    float* out = (float*)d_out;                 // [8192, 128]

    cudaFuncSetAttribute(k_attn,   cudaFuncAttributeMaxDynamicSharedMemorySize, SMEM_BYTES);
    cudaFuncSetAttribute(k_gemm1h, cudaFuncAttributeMaxDynamicSharedMemorySize, SMEM_G1);

    k_prep   <<<(N_GENES * D_MODEL / 4) / 256, 256>>>(inp, W);   // launch 1
    k_gemm1h <<<N_GENES / 128, 256, SMEM_G1>>>(a);               // launch 2 (+F tables)
    k_factG  <<<N_REG / 256, 256>>>();                           // launch 3 (G tables)
    k_attn   <<<GRID_ATTN, 256, SMEM_BYTES>>>(adj);              // launch 4 (ncu target)
    k_combine<<<(N_REG * OUT_DIM / 4) / 256, 256>>>(out);        // launch 5
}

// round 16
// speedup vs baseline: 1.3316x; 1.0067x over previous
#include <cuda_runtime.h>
#include <cuda_fp16.h>
#include <cstdint>

#define N_GENES 16384
#define N_REG   8192
#define D_MODEL 256
#define OUT_DIM 128
#define ALPHA   0.2f

#define TI 64
#define TJ 64
#define NTJ 256
#define N_ITILES (N_REG / TI)
#define NJOBS (N_ITILES * NTJ)
#define NQUADS (NJOBS / 4)
#define GRID_ATTN 304

#define SM_P    0
#define SM_V    16384
#define SMEM_BYTES 81920
#define SMEM_G2 98304          // gemm1h: 2 x 32KB fp32-A stages + 2 x 16KB fp16-B stages

// ---------------- device scratch ----------------
__device__ __align__(16) __half g_Wh  [D_MODEL * OUT_DIM];  // W fp16
__device__ __align__(16) __half g_whh [N_GENES * OUT_DIM];  // w_h fp16
__device__ float  g_wh1[N_REG];
__device__ float  g_wh2[N_GENES];
__device__ float  g_F1 [N_GENES];
__device__ float  g_F2 [N_GENES];
__device__ float  g_G1 [N_REG];
__device__ float  g_G2 [N_REG];
__device__ unsigned g_w2max_bits;
__device__ float  g_D  [(size_t)N_REG * OUT_DIM];
__device__ float  g_S  [N_REG];

// ---------------- helpers ----------------
static __device__ __forceinline__ uint32_t swz(uint32_t x) { return x ^ ((x >> 3) & 0x70); }
static __device__ __forceinline__ uint32_t smem_u32(const void* p) {
    return (uint32_t)__cvta_generic_to_shared(p);
}
static __device__ __forceinline__ unsigned fenc(float f) {
    unsigned u = __float_as_uint(f);
    return (u & 0x80000000u) ? ~u : (u | 0x80000000u);
}
static __device__ __forceinline__ float fdec(unsigned k) {
    unsigned u = (k & 0x80000000u) ? (k ^ 0x80000000u) : ~k;
    return __uint_as_float(u);
}

// ---------------- K1: prep — W fp16 + zero D/S ----------------
__global__ void k_prep(const float* __restrict__ W) {
    const int t = blockIdx.x * 256 + threadIdx.x;    // 0 .. 262143
    if (t == 0) g_w2max_bits = 0u;
    ((float4*)g_D)[t] = make_float4(0.f, 0.f, 0.f, 0.f);
    if (t < (D_MODEL * OUT_DIM) / 4) {
        float4 v = *(const float4*)&W[t * 4];
        __half2 h0 = __floats2half2_rn(v.x, v.y);
        __half2 h1 = __floats2half2_rn(v.z, v.w);
        uint2 u; u.x = *(uint32_t*)&h0; u.y = *(uint32_t*)&h1;
        *(uint2*)&g_Wh[t * 4] = u;
    }
    if (t < N_REG) g_S[t] = 0.f;
}

// ---------------- K2: w_h = inp @ W via HMMA, inp converted in-kernel ----------------
// smem: A32 stages (fp32, swizzled 16B units) at st*32768; B16 stages at 65536 + st*16384.
__global__ void __launch_bounds__(256, 1)
k_gemm1h(const float* __restrict__ inp, const float* __restrict__ a) {
    extern __shared__ char smem[];
    const uint32_t sb = smem_u32(smem);
    float* sP1 = (float*)(smem);            // reuse stage-0 region post-mainloop
    float* sP2 = (float*)(smem + 1024);

    const int t    = threadIdx.x;
    const int lane = t & 31, warp = t >> 5;
    const int wi   = warp >> 1, wc = warp & 1;    // warp tile: rows wi*32, cols wc*64
    const int r0   = blockIdx.x * 128;

    auto load_chunk = [&](int kc, int st) {
        const uint32_t AB = sb + st * 32768;
        const uint32_t BB = sb + 65536 + st * 16384;
        // A fp32: 128 rows x 64 floats (256B rows, swizzled); 8 x 16B per thread
        #pragma unroll
        for (int u = 0; u < 8; u++) {
            const int idx = t + u * 256;
            const int row = idx >> 4, unit = idx & 15;
            const float* src = &inp[(size_t)(r0 + row) * D_MODEL + kc * 64 + unit * 4];
            asm volatile("cp.async.cg.shared.global [%0], [%1], 16;"
                         :: "r"(AB + swz(row * 256 + unit * 16)), "l"(src));
        }
        // B fp16: 64 k-rows x 128 halves (2 atoms of 64 cols)
        #pragma unroll
        for (int u = 0; u < 4; u++) {
            const int idx = t + u * 256;
            const int row = idx >> 4, seg = idx & 15;
            const __half* src = &g_Wh[(kc * 64 + row) * OUT_DIM + seg * 8];
            const uint32_t dst = BB + (seg >> 3) * 8192 + swz(row * 128 + (seg & 7) * 16);
            asm volatile("cp.async.cg.shared.global [%0], [%1], 16;" :: "r"(dst), "l"(src));
        }
        asm volatile("cp.async.commit_group;" ::: "memory");
    };

    float d[2][8][4];
    #pragma unroll
    for (int ah = 0; ah < 2; ah++)
        #pragma unroll
        for (int n = 0; n < 8; n++)
            #pragma unroll
            for (int k = 0; k < 4; k++) d[ah][n][k] = 0.f;

    load_chunk(0, 0);
    #pragma unroll
    for (int kc = 0; kc < 4; kc++) {
        if (kc + 1 < 4) load_chunk(kc + 1, (kc + 1) & 1);
        if (kc + 1 < 4) asm volatile("cp.async.wait_group 1;" ::: "memory");
        else            asm volatile("cp.async.wait_group 0;" ::: "memory");
        __syncthreads();

        const uint32_t AB = sb + (kc & 1) * 32768;
        const uint32_t BB = sb + 65536 + (kc & 1) * 16384;
        #pragma unroll
        for (int ks = 0; ks < 4; ks++) {
            // A fragments: fp32 LDS.64 + convert (conflict-free under swz)
            uint32_t afr[2][4];
            #pragma unroll
            for (int ah = 0; ah < 2; ah++)
                #pragma unroll
                for (int k = 0; k < 4; k++) {
                    const int row = wi * 32 + ah * 16 + (lane >> 2) + (k & 1) * 8;
                    const int col = ks * 16 + (lane & 3) * 2 + (k >> 1) * 8;
                    float2 f;
                    asm volatile("ld.shared.v2.f32 {%0,%1}, [%2];"
                                 : "=f"(f.x), "=f"(f.y)
                                 : "r"(AB + swz(row * 256 + col * 4)));
                    __half2 h = __floats2half2_rn(f.x, f.y);
                    afr[ah][k] = *(uint32_t*)&h;
                }
            uint32_t bfr[4][4];
            #pragma unroll
            for (int nb = 0; nb < 4; nb++) {
                const int cin = nb * 16 + (lane >> 4) * 8;
                const uint32_t baddr = BB + wc * 8192
                                     + swz((ks * 16 + (lane & 15)) * 128 + cin * 2);
                asm volatile("ldmatrix.sync.aligned.m8n8.x4.trans.shared.b16 {%0,%1,%2,%3},[%4];\n"
                             : "=r"(bfr[nb][0]), "=r"(bfr[nb][1]),
                               "=r"(bfr[nb][2]), "=r"(bfr[nb][3]) : "r"(baddr));
            }
            #pragma unroll
            for (int ah = 0; ah < 2; ah++)
                #pragma unroll
                for (int n = 0; n < 8; n++) {
                    asm volatile(
                        "mma.sync.aligned.m16n8k16.row.col.f32.f16.f16.f32 "
                        "{%0,%1,%2,%3},{%4,%5,%6,%7},{%8,%9},{%0,%1,%2,%3};\n"
                        : "+f"(d[ah][n][0]), "+f"(d[ah][n][1]),
                          "+f"(d[ah][n][2]), "+f"(d[ah][n][3])
                        : "r"(afr[ah][0]), "r"(afr[ah][1]), "r"(afr[ah][2]), "r"(afr[ah][3]),
                          "r"(bfr[n >> 1][(n & 1) * 2]), "r"(bfr[n >> 1][(n & 1) * 2 + 1]));
                }
        }
        __syncthreads();   // reads done before this stage is reloaded (kc+2)
    }

    // ---- epilogue: store w_h fp16 + fused wh1/wh2 + F tables + block max ----
    float s1[2][2] = {{0.f,0.f},{0.f,0.f}}, s2[2][2] = {{0.f,0.f},{0.f,0.f}};
    #pragma unroll
    for (int ah = 0; ah < 2; ah++) {
        const int r1 = wi * 32 + ah * 16 + (lane >> 2);
        #pragma unroll
        for (int n = 0; n < 8; n++) {
            const int c = wc * 64 + n * 8 + (lane & 3) * 2;
            __half2 h0 = __floats2half2_rn(d[ah][n][0], d[ah][n][1]);
            __half2 h1 = __floats2half2_rn(d[ah][n][2], d[ah][n][3]);
            *(uint32_t*)&g_whh[(size_t)(r0 + r1) * OUT_DIM + c]     = *(uint32_t*)&h0;
            *(uint32_t*)&g_whh[(size_t)(r0 + r1 + 8) * OUT_DIM + c] = *(uint32_t*)&h1;
            const float a10 = a[c], a11 = a[c + 1];
            const float a20 = a[OUT_DIM + c], a21 = a[OUT_DIM + c + 1];
            s1[ah][0] += d[ah][n][0] * a10 + d[ah][n][1] * a11;
            s2[ah][0] += d[ah][n][0] * a20 + d[ah][n][1] * a21;
            s1[ah][1] += d[ah][n][2] * a10 + d[ah][n][3] * a11;
            s2[ah][1] += d[ah][n][2] * a20 + d[ah][n][3] * a21;
        }
    }
    __syncthreads();
    #pragma unroll
    for (int ah = 0; ah < 2; ah++)
        #pragma unroll
        for (int h = 0; h < 2; h++) {
            float v1 = s1[ah][h], v2 = s2[ah][h];
            v1 += __shfl_xor_sync(0xffffffffu, v1, 1);
            v1 += __shfl_xor_sync(0xffffffffu, v1, 2);
            v2 += __shfl_xor_sync(0xffffffffu, v2, 1);
            v2 += __shfl_xor_sync(0xffffffffu, v2, 2);
            if ((lane & 3) == 0) {
                const int row = wi * 32 + ah * 16 + h * 8 + (lane >> 2);
                sP1[wc * 128 + row] = v1;
                sP2[wc * 128 + row] = v2;
            }
        }
    __syncthreads();
    __shared__ float smax[4];
    if (t < 128) {
        const float v1 = sP1[t] + sP1[128 + t];
        const float v2 = sP2[t] + sP2[128 + t];
        if (r0 + t < N_REG) g_wh1[r0 + t] = v1;
        g_wh2[r0 + t] = v2;
        g_F1[r0 + t] = expf(v2);              // F tables need no global max
        g_F2[r0 + t] = expf(ALPHA * v2);
        float m = v2;
        #pragma unroll
        for (int o = 16; o; o >>= 1) m = fmaxf(m, __shfl_xor_sync(0xffffffffu, m, o));
        if ((t & 31) == 0) smax[t >> 5] = m;
    }
    __syncthreads();
    if (t == 0) {
        float m = fmaxf(fmaxf(smax[0], smax[1]), fmaxf(smax[2], smax[3]));
        atomicMax(&g_w2max_bits, fenc(m));
    }
}

// ---------------- K3: G1/G2 tables (needs global max) ----------------
__global__ void k_factG() {
    const int j = blockIdx.x * 256 + threadIdx.x;     // 0..8191
    const float w2m = fdec(g_w2max_bits);
    float w1 = g_wh1[j];
    float x  = w1 + w2m;
    float B  = x > 0.f ? x : ALPHA * x;
    g_G1[j] = expf(w1 - B);
    g_G2[j] = expf(ALPHA * w1 - B);
}

// ---------------- K4: persistent fused masked-softmax attention (proven body) -----------
__global__ void __launch_bounds__(256, 2)
k_attn(const float* __restrict__ adj) {
    extern __shared__ char smem[];
    const uint32_t sb = smem_u32(smem);

    const int t    = threadIdx.x;
    const int lane = t & 31, warp = t >> 5;
    const int rh   = lane >> 4;
    const int q    = lane & 15;
    const int wi   = warp >> 2, wc = warp & 3;

    const int s = 4 * (int)(((long long)blockIdx.x * NQUADS) / GRID_ATTN);
    const int e = 4 * (int)(((long long)(blockIdx.x + 1) * NQUADS) / GRID_ATTN);

    auto load_stage = [&](int m, int slot) {
        if (m < e) {
            const uint32_t VB = sb + SM_V + slot * 16384;
            const int jo = (m & (NTJ - 1)) * TJ;
            #pragma unroll
            for (int u = 0; u < 4; u++) {
                const int idx = t + u * 256;
                const int row = idx >> 4, seg = idx & 15;
                const __half* src = &g_whh[(size_t)(jo + row) * OUT_DIM + seg * 8];
                const uint32_t dst = VB + (seg >> 3) * 8192 + swz(row * 128 + (seg & 7) * 16);
                asm volatile("cp.async.cg.shared.global [%0], [%1], 16;" :: "r"(dst), "l"(src));
            }
        }
        asm volatile("cp.async.commit_group;" ::: "memory");
    };

    float4 av[4], f1q, f2q;
    auto prefetch = [&](int m) {
        if (m < e) {
            const int jo = (m & (NTJ - 1)) * TJ;
            const float* base = adj + ((size_t)(m >> 8) * TI + warp * 8 + rh * 4) * N_GENES
                              + jo + q * 4;
            #pragma unroll
            for (int r = 0; r < 4; r++)
                av[r] = __ldg((const float4*)(base + (size_t)r * N_GENES));
            f1q = *(const float4*)&g_F1[jo + q * 4];
            f2q = *(const float4*)&g_F2[jo + q * 4];
        }
    };

    float G1r[4], G2r[4], sacc[4];
    float d[2][4][4];
    uint32_t dh[2][4][2];

    auto load_row_consts = [&](int it) {
        #pragma unroll
        for (int r = 0; r < 4; r++) {
            const int i = it * TI + warp * 8 + rh * 4 + r;
            G1r[r] = g_G1[i];
            G2r[r] = g_G2[i];
            sacc[r] = 0.f;
        }
    };
    auto reset_D = [&]() {
        #pragma unroll
        for (int ah = 0; ah < 2; ah++)
            #pragma unroll
            for (int n = 0; n < 4; n++) {
                d[ah][n][0] = d[ah][n][1] = d[ah][n][2] = d[ah][n][3] = 0.f;
                dh[ah][n][0] = dh[ah][n][1] = 0u;
            }
    };
    auto fold = [&]() {
        #pragma unroll
        for (int ah = 0; ah < 2; ah++)
            #pragma unroll
            for (int n = 0; n < 4; n++) {
                float2 lo = __half22float2(*(__half2*)&dh[ah][n][0]);
                float2 hi = __half22float2(*(__half2*)&dh[ah][n][1]);
                d[ah][n][0] += lo.x; d[ah][n][1] += lo.y;
                d[ah][n][2] += hi.x; d[ah][n][3] += hi.y;
                dh[ah][n][0] = 0u;   dh[ah][n][1] = 0u;
            }
    };
    auto flush_S = [&](int it) {
        #pragma unroll
        for (int r = 0; r < 4; r++) {
            float v = sacc[r];
            v += __shfl_xor_sync(0xffffffffu, v, 8);
            v += __shfl_xor_sync(0xffffffffu, v, 4);
            v += __shfl_xor_sync(0xffffffffu, v, 2);
            v += __shfl_xor_sync(0xffffffffu, v, 1);
            if (q == 0) atomicAdd(&g_S[it * TI + warp * 8 + rh * 4 + r], v);
        }
    };
    auto flush_D = [&](int it) {
        fold();
        #pragma unroll
        for (int ah = 0; ah < 2; ah++) {
            const int r1 = wi * 32 + ah * 16 + (lane >> 2);
            #pragma unroll
            for (int n = 0; n < 4; n++) {
                const int c = wc * 32 + n * 8 + (lane & 3) * 2;
                float* p0 = &g_D[(size_t)(it * TI + r1) * OUT_DIM + c];
                float* p1 = &g_D[(size_t)(it * TI + r1 + 8) * OUT_DIM + c];
                atomicAdd(p0,     d[ah][n][0]);
                atomicAdd(p0 + 1, d[ah][n][1]);
                atomicAdd(p1,     d[ah][n][2]);
                atomicAdd(p1 + 1, d[ah][n][3]);
                d[ah][n][0] = d[ah][n][1] = d[ah][n][2] = d[ah][n][3] = 0.f;
            }
        }
    };
    auto build_P = [&](int m, uint32_t PB) {
        #pragma unroll
        for (int r = 0; r < 4; r++) {
            const float G1 = G1r[r], G2 = G2r[r];
            float p0 = av[r].x * fmaxf(G1 * f1q.x, G2 * f2q.x);
            float p1 = av[r].y * fmaxf(G1 * f1q.y, G2 * f2q.y);
            float p2 = av[r].z * fmaxf(G1 * f1q.z, G2 * f2q.z);
            float p3 = av[r].w * fmaxf(G1 * f1q.w, G2 * f2q.w);
            sacc[r] += (p0 + p1) + (p2 + p3);
            __half2 h01 = __floats2half2_rn(p0, p1);
            __half2 h23 = __floats2half2_rn(p2, p3);
            asm volatile("st.shared.v2.b32 [%0], {%1, %2};"
                         :: "r"(PB + swz((warp * 8 + rh * 4 + r) * 128 + q * 8)),
                            "r"(*(uint32_t*)&h01), "r"(*(uint32_t*)&h23));
        }
    };

    prefetch(s);
    load_stage(s, 0);
    load_stage(s + 1, 1);
    load_stage(s + 2, 2);
    int it_b = s >> 8;
    load_row_consts(it_b);
    reset_D();
    build_P(s, sb + SM_P);
    prefetch(s + 1);

    for (int mb = s; mb < e; mb += 4) {
        #pragma unroll
        for (int u = 0; u < 4; u++) {
            const int m = mb + u;
            const uint32_t PB = sb + SM_P + (u & 1) * 8192;
            const uint32_t VB = sb + SM_V + u * 16384;

            asm volatile("cp.async.wait_group 2;" ::: "memory");
            __syncthreads();

            load_stage(m + 3, (u + 3) & 3);

            if (m + 1 < e) {
                if (u == 3) {
                    const int it_n = (m + 1) >> 8;
                    if (it_n != it_b) {
                        flush_S(it_b);
                        it_b = it_n;
                        load_row_consts(it_b);
                    }
                }
                build_P(m + 1, sb + SM_P + ((u + 1) & 1) * 8192);
                prefetch(m + 2);
            }

            #pragma unroll
            for (int ks = 0; ks < 4; ks++) {
                uint32_t afr[2][4];
                #pragma unroll
                for (int ah = 0; ah < 2; ah++) {
                    const uint32_t aaddr = PB + swz((wi * 32 + ah * 16 + (lane & 15)) * 128
                                                    + ks * 32 + (lane >> 4) * 16);
                    asm volatile("ldmatrix.sync.aligned.m8n8.x4.shared.b16 {%0,%1,%2,%3},[%4];\n"
                                 : "=r"(afr[ah][0]), "=r"(afr[ah][1]),
                                   "=r"(afr[ah][2]), "=r"(afr[ah][3]) : "r"(aaddr));
                }
                uint32_t bfr[8];
                const int atom = wc >> 1;
                const int cin0 = (wc & 1) * 32 + (lane >> 4) * 8;
                const uint32_t brow = (ks * 16 + (lane & 15)) * 128;
                const uint32_t baddr0 = VB + atom * 8192 + swz(brow + cin0 * 2);
                asm volatile("ldmatrix.sync.aligned.m8n8.x4.trans.shared.b16 {%0,%1,%2,%3},[%4];\n"
                             : "=r"(bfr[0]), "=r"(bfr[1]), "=r"(bfr[2]), "=r"(bfr[3]) : "r"(baddr0));
                const uint32_t baddr1 = VB + atom * 8192 + swz(brow + (cin0 + 16) * 2);
                asm volatile("ldmatrix.sync.aligned.m8n8.x4.trans.shared.b16 {%0,%1,%2,%3},[%4];\n"
                             : "=r"(bfr[4]), "=r"(bfr[5]), "=r"(bfr[6]), "=r"(bfr[7]) : "r"(baddr1));
                #pragma unroll
                for (int ah = 0; ah < 2; ah++)
                    #pragma unroll
                    for (int n = 0; n < 4; n++) {
                        asm volatile(
                            "mma.sync.aligned.m16n8k16.row.col.f16.f16.f16.f16 "
                            "{%0,%1},{%2,%3,%4,%5},{%6,%7},{%0,%1};\n"
                            : "+r"(dh[ah][n][0]), "+r"(dh[ah][n][1])
                            : "r"(afr[ah][0]), "r"(afr[ah][1]), "r"(afr[ah][2]), "r"(afr[ah][3]),
                              "r"(bfr[n * 2]), "r"(bfr[n * 2 + 1]));
                    }
            }

            if (u == 3) {
                if (m + 1 == e || ((m + 1) & (NTJ - 1)) == 0) {
                    flush_D(m >> 8);
                } else {
                    fold();
                }
            }
        }
    }
    flush_S(it_b);
}

// ---------------- K5: normalize + ELU (float4) ----------------
__global__ void k_combine(float* __restrict__ out) {
    const int idx = blockIdx.x * 256 + threadIdx.x;   // 0..262143, one float4 each
    const int row = idx >> 5, c4 = idx & 31;
    const float inv = 1.0f / g_S[row];
    float4 v = *(const float4*)&g_D[(size_t)row * OUT_DIM + c4 * 4];
    v.x *= inv; v.y *= inv; v.z *= inv; v.w *= inv;
    float4 o;
    o.x = v.x > 0.f ? v.x : expm1f(v.x);
    o.y = v.y > 0.f ? v.y : expm1f(v.y);
    o.z = v.z > 0.f ? v.z : expm1f(v.z);
    o.w = v.w > 0.f ? v.w : expm1f(v.w);
    *(float4*)&out[(size_t)row * OUT_DIM + c4 * 4] = o;
}

// ---------------- launch ----------------
extern "C" void kernel_launch(void* const* d_in, const int* in_sizes, int n_in,
                              void* d_out, int out_size) {
    const float* inp = (const float*)d_in[0];   // [16384, 256]
    const float* adj = (const float*)d_in[1];   // [8192, 16384]
    const float* W   = (const float*)d_in[2];   // [256, 128]
    const float* a   = (const float*)d_in[3];   // [256, 1]
    float* out = (float*)d_out;                 // [8192, 128]

    cudaFuncSetAttribute(k_attn,   cudaFuncAttributeMaxDynamicSharedMemorySize, SMEM_BYTES);
    cudaFuncSetAttribute(k_gemm1h, cudaFuncAttributeMaxDynamicSharedMemorySize, SMEM_G2);

    k_prep   <<<1024, 256>>>(W);                             // launch 1 (W fp16 + zero D/S)
    k_gemm1h <<<N_GENES / 128, 256, SMEM_G2>>>(inp, a);      // launch 2 (fused convert)
    k_factG  <<<N_REG / 256, 256>>>();                       // launch 3 (G tables)
    k_attn   <<<GRID_ATTN, 256, SMEM_BYTES>>>(adj);          // launch 4 (ncu target)
    k_combine<<<(N_REG * OUT_DIM / 4) / 256, 256>>>(out);    // launch 5
}

// round 17
// speedup vs baseline: 1.4110x; 1.0597x over previous
#include <cuda_runtime.h>
#include <cuda_fp16.h>
#include <cstdint>

#define N_GENES 16384
#define N_REG   8192
#define D_MODEL 256
#define OUT_DIM 128
#define ALPHA   0.2f

#define TI 64
#define TJ 64
#define NTJ 256
#define N_ITILES (N_REG / TI)
#define NJOBS (N_ITILES * NTJ)
#define NQUADS (NJOBS / 4)
#define GRID_ATTN 304

#define SM_P    0
#define SM_V    16384
#define SMEM_BYTES 81920
#define SMEM_G2 98304          // gemm1h: 2 x 32KB fp32-A stages + 2 x 16KB fp16-B stages

// ---------------- device scratch ----------------
__device__ __align__(16) __half g_Wh  [D_MODEL * OUT_DIM];  // W fp16
__device__ __align__(16) __half g_whh [N_GENES * OUT_DIM];  // w_h fp16
__device__ float  g_wh1[N_REG];
__device__ float  g_wh2[N_GENES];
__device__ __align__(16) uint2 g_Fh[N_GENES / 2];           // {F1h2, F2h2} per j-pair
__device__ uint32_t g_Gh[N_REG];                            // {G1h, G2h} per row
__device__ unsigned g_w2max_bits;
__device__ float  g_D  [(size_t)N_REG * OUT_DIM];
__device__ float  g_S  [N_REG];

// ---------------- helpers ----------------
static __device__ __forceinline__ uint32_t swz(uint32_t x) { return x ^ ((x >> 3) & 0x70); }
static __device__ __forceinline__ uint32_t smem_u32(const void* p) {
    return (uint32_t)__cvta_generic_to_shared(p);
}
static __device__ __forceinline__ unsigned fenc(float f) {
    unsigned u = __float_as_uint(f);
    return (u & 0x80000000u) ? ~u : (u | 0x80000000u);
}
static __device__ __forceinline__ float fdec(unsigned k) {
    unsigned u = (k & 0x80000000u) ? (k ^ 0x80000000u) : ~k;
    return __uint_as_float(u);
}

// ---------------- K1: prep — W fp16 + zero D/S ----------------
__global__ void k_prep(const float* __restrict__ W) {
    const int t = blockIdx.x * 256 + threadIdx.x;    // 0 .. 262143
    if (t == 0) g_w2max_bits = 0u;
    ((float4*)g_D)[t] = make_float4(0.f, 0.f, 0.f, 0.f);
    if (t < (D_MODEL * OUT_DIM) / 4) {
        float4 v = *(const float4*)&W[t * 4];
        __half2 h0 = __floats2half2_rn(v.x, v.y);
        __half2 h1 = __floats2half2_rn(v.z, v.w);
        uint2 u; u.x = *(uint32_t*)&h0; u.y = *(uint32_t*)&h1;
        *(uint2*)&g_Wh[t * 4] = u;
    }
    if (t < N_REG) g_S[t] = 0.f;
}

// ---------------- K2: w_h = inp @ W via HMMA, inp converted in-kernel ----------------
__global__ void __launch_bounds__(256, 1)
k_gemm1h(const float* __restrict__ inp, const float* __restrict__ a) {
    extern __shared__ char smem[];
    const uint32_t sb = smem_u32(smem);
    float* sP1 = (float*)(smem);
    float* sP2 = (float*)(smem + 1024);

    const int t    = threadIdx.x;
    const int lane = t & 31, warp = t >> 5;
    const int wi   = warp >> 1, wc = warp & 1;
    const int r0   = blockIdx.x * 128;

    auto load_chunk = [&](int kc, int st) {
        const uint32_t AB = sb + st * 32768;
        const uint32_t BB = sb + 65536 + st * 16384;
        #pragma unroll
        for (int u = 0; u < 8; u++) {
            const int idx = t + u * 256;
            const int row = idx >> 4, unit = idx & 15;
            const float* src = &inp[(size_t)(r0 + row) * D_MODEL + kc * 64 + unit * 4];
            asm volatile("cp.async.cg.shared.global [%0], [%1], 16;"
                         :: "r"(AB + swz(row * 256 + unit * 16)), "l"(src));
        }
        #pragma unroll
        for (int u = 0; u < 4; u++) {
            const int idx = t + u * 256;
            const int row = idx >> 4, seg = idx & 15;
            const __half* src = &g_Wh[(kc * 64 + row) * OUT_DIM + seg * 8];
            const uint32_t dst = BB + (seg >> 3) * 8192 + swz(row * 128 + (seg & 7) * 16);
            asm volatile("cp.async.cg.shared.global [%0], [%1], 16;" :: "r"(dst), "l"(src));
        }
        asm volatile("cp.async.commit_group;" ::: "memory");
    };

    float d[2][8][4];
    #pragma unroll
    for (int ah = 0; ah < 2; ah++)
        #pragma unroll
        for (int n = 0; n < 8; n++)
            #pragma unroll
            for (int k = 0; k < 4; k++) d[ah][n][k] = 0.f;

    load_chunk(0, 0);
    #pragma unroll
    for (int kc = 0; kc < 4; kc++) {
        if (kc + 1 < 4) load_chunk(kc + 1, (kc + 1) & 1);
        if (kc + 1 < 4) asm volatile("cp.async.wait_group 1;" ::: "memory");
        else            asm volatile("cp.async.wait_group 0;" ::: "memory");
        __syncthreads();

        const uint32_t AB = sb + (kc & 1) * 32768;
        const uint32_t BB = sb + 65536 + (kc & 1) * 16384;
        #pragma unroll
        for (int ks = 0; ks < 4; ks++) {
            uint32_t afr[2][4];
            #pragma unroll
            for (int ah = 0; ah < 2; ah++)
                #pragma unroll
                for (int k = 0; k < 4; k++) {
                    const int row = wi * 32 + ah * 16 + (lane >> 2) + (k & 1) * 8;
                    const int col = ks * 16 + (lane & 3) * 2 + (k >> 1) * 8;
                    float2 f;
                    asm volatile("ld.shared.v2.f32 {%0,%1}, [%2];"
                                 : "=f"(f.x), "=f"(f.y)
                                 : "r"(AB + swz(row * 256 + col * 4)));
                    __half2 h = __floats2half2_rn(f.x, f.y);
                    afr[ah][k] = *(uint32_t*)&h;
                }
            uint32_t bfr[4][4];
            #pragma unroll
            for (int nb = 0; nb < 4; nb++) {
                const int cin = nb * 16 + (lane >> 4) * 8;
                const uint32_t baddr = BB + wc * 8192
                                     + swz((ks * 16 + (lane & 15)) * 128 + cin * 2);
                asm volatile("ldmatrix.sync.aligned.m8n8.x4.trans.shared.b16 {%0,%1,%2,%3},[%4];\n"
                             : "=r"(bfr[nb][0]), "=r"(bfr[nb][1]),
                               "=r"(bfr[nb][2]), "=r"(bfr[nb][3]) : "r"(baddr));
            }
            #pragma unroll
            for (int ah = 0; ah < 2; ah++)
                #pragma unroll
                for (int n = 0; n < 8; n++) {
                    asm volatile(
                        "mma.sync.aligned.m16n8k16.row.col.f32.f16.f16.f32 "
                        "{%0,%1,%2,%3},{%4,%5,%6,%7},{%8,%9},{%0,%1,%2,%3};\n"
                        : "+f"(d[ah][n][0]), "+f"(d[ah][n][1]),
                          "+f"(d[ah][n][2]), "+f"(d[ah][n][3])
                        : "r"(afr[ah][0]), "r"(afr[ah][1]), "r"(afr[ah][2]), "r"(afr[ah][3]),
                          "r"(bfr[n >> 1][(n & 1) * 2]), "r"(bfr[n >> 1][(n & 1) * 2 + 1]));
                }
        }
        __syncthreads();
    }

    float s1[2][2] = {{0.f,0.f},{0.f,0.f}}, s2[2][2] = {{0.f,0.f},{0.f,0.f}};
    #pragma unroll
    for (int ah = 0; ah < 2; ah++) {
        const int r1 = wi * 32 + ah * 16 + (lane >> 2);
        #pragma unroll
        for (int n = 0; n < 8; n++) {
            const int c = wc * 64 + n * 8 + (lane & 3) * 2;
            __half2 h0 = __floats2half2_rn(d[ah][n][0], d[ah][n][1]);
            __half2 h1 = __floats2half2_rn(d[ah][n][2], d[ah][n][3]);
            *(uint32_t*)&g_whh[(size_t)(r0 + r1) * OUT_DIM + c]     = *(uint32_t*)&h0;
            *(uint32_t*)&g_whh[(size_t)(r0 + r1 + 8) * OUT_DIM + c] = *(uint32_t*)&h1;
            const float a10 = a[c], a11 = a[c + 1];
            const float a20 = a[OUT_DIM + c], a21 = a[OUT_DIM + c + 1];
            s1[ah][0] += d[ah][n][0] * a10 + d[ah][n][1] * a11;
            s2[ah][0] += d[ah][n][0] * a20 + d[ah][n][1] * a21;
            s1[ah][1] += d[ah][n][2] * a10 + d[ah][n][3] * a11;
            s2[ah][1] += d[ah][n][2] * a20 + d[ah][n][3] * a21;
        }
    }
    __syncthreads();
    #pragma unroll
    for (int ah = 0; ah < 2; ah++)
        #pragma unroll
        for (int h = 0; h < 2; h++) {
            float v1 = s1[ah][h], v2 = s2[ah][h];
            v1 += __shfl_xor_sync(0xffffffffu, v1, 1);
            v1 += __shfl_xor_sync(0xffffffffu, v1, 2);
            v2 += __shfl_xor_sync(0xffffffffu, v2, 1);
            v2 += __shfl_xor_sync(0xffffffffu, v2, 2);
            if ((lane & 3) == 0) {
                const int row = wi * 32 + ah * 16 + h * 8 + (lane >> 2);
                sP1[wc * 128 + row] = v1;
                sP2[wc * 128 + row] = v2;
            }
        }
    __syncthreads();
    __shared__ float smax[4];
    if (t < 128) {
        const float v1 = sP1[t] + sP1[128 + t];
        const float v2 = sP2[t] + sP2[128 + t];
        if (r0 + t < N_REG) g_wh1[r0 + t] = v1;
        g_wh2[r0 + t] = v2;
        float m = v2;
        #pragma unroll
        for (int o = 16; o; o >>= 1) m = fmaxf(m, __shfl_xor_sync(0xffffffffu, m, o));
        if ((t & 31) == 0) smax[t >> 5] = m;
    }
    __syncthreads();
    if (t == 0) {
        float m = fmaxf(fmaxf(smax[0], smax[1]), fmaxf(smax[2], smax[3]));
        atomicMax(&g_w2max_bits, fenc(m));
    }
}

// ---------------- K3: packed fp16 factor tables (all factors <= 1) ----------------
__global__ void k_factG() {
    const int p = blockIdx.x * 256 + threadIdx.x;     // 0..8191
    const float w2m = fdec(g_w2max_bits);
    // F pair for columns 2p, 2p+1 (rescaled: F1' = exp(w2-w2m), F2' = exp(a(w2-w2m)))
    const float w2a = g_wh2[2 * p], w2b = g_wh2[2 * p + 1];
    __half2 f1 = __floats2half2_rn(expf(w2a - w2m), expf(w2b - w2m));
    __half2 f2 = __floats2half2_rn(expf(ALPHA * (w2a - w2m)), expf(ALPHA * (w2b - w2m)));
    uint2 u; u.x = *(uint32_t*)&f1; u.y = *(uint32_t*)&f2;
    g_Fh[p] = u;
    // G for row p (rescaled: G1' = exp(x-B), G2' = exp(a*x-B); x = w1+w2m, B = lrelu(x))
    const float w1 = g_wh1[p];
    const float x  = w1 + w2m;
    const float B  = x > 0.f ? x : ALPHA * x;
    __half2 g = __floats2half2_rn(expf(x - B), expf(ALPHA * x - B));
    g_Gh[p] = *(uint32_t*)&g;
}

// ---------------- K4: persistent fused masked-softmax attention (half2 P-build) ---------
__global__ void __launch_bounds__(256, 2)
k_attn(const float* __restrict__ adj) {
    extern __shared__ char smem[];
    const uint32_t sb = smem_u32(smem);

    const int t    = threadIdx.x;
    const int lane = t & 31, warp = t >> 5;
    const int rh   = lane >> 4;
    const int q    = lane & 15;
    const int wi   = warp >> 2, wc = warp & 3;

    const int s = 4 * (int)(((long long)blockIdx.x * NQUADS) / GRID_ATTN);
    const int e = 4 * (int)(((long long)(blockIdx.x + 1) * NQUADS) / GRID_ATTN);

    auto load_stage = [&](int m, int slot) {
        if (m < e) {
            const uint32_t VB = sb + SM_V + slot * 16384;
            const int jo = (m & (NTJ - 1)) * TJ;
            #pragma unroll
            for (int u = 0; u < 4; u++) {
                const int idx = t + u * 256;
                const int row = idx >> 4, seg = idx & 15;
                const __half* src = &g_whh[(size_t)(jo + row) * OUT_DIM + seg * 8];
                const uint32_t dst = VB + (seg >> 3) * 8192 + swz(row * 128 + (seg & 7) * 16);
                asm volatile("cp.async.cg.shared.global [%0], [%1], 16;" :: "r"(dst), "l"(src));
            }
        }
        asm volatile("cp.async.commit_group;" ::: "memory");
    };

    float4 av[4];
    uint4 fqr;   // {F1h2(j01), F2h2(j01), F1h2(j23), F2h2(j23)}
    auto prefetch = [&](int m) {
        if (m < e) {
            const int jo = (m & (NTJ - 1)) * TJ;
            const float* base = adj + ((size_t)(m >> 8) * TI + warp * 8 + rh * 4) * N_GENES
                              + jo + q * 4;
            #pragma unroll
            for (int r = 0; r < 4; r++)
                av[r] = __ldg((const float4*)(base + (size_t)r * N_GENES));
            fqr = *(const uint4*)&g_Fh[(jo + q * 4) >> 1];
        }
    };

    __half2 G1b[4], G2b[4];
    float sacc[4];
    float d[2][4][4];
    uint32_t dh[2][4][2];

    auto load_row_consts = [&](int it) {
        #pragma unroll
        for (int r = 0; r < 4; r++) {
            const int i = it * TI + warp * 8 + rh * 4 + r;
            uint32_t gh = g_Gh[i];
            __half2 g = *(__half2*)&gh;
            G1b[r] = __half2half2(__low2half(g));
            G2b[r] = __half2half2(__high2half(g));
            sacc[r] = 0.f;
        }
    };
    auto reset_D = [&]() {
        #pragma unroll
        for (int ah = 0; ah < 2; ah++)
            #pragma unroll
            for (int n = 0; n < 4; n++) {
                d[ah][n][0] = d[ah][n][1] = d[ah][n][2] = d[ah][n][3] = 0.f;
                dh[ah][n][0] = dh[ah][n][1] = 0u;
            }
    };
    auto fold = [&]() {
        #pragma unroll
        for (int ah = 0; ah < 2; ah++)
            #pragma unroll
            for (int n = 0; n < 4; n++) {
                float2 lo = __half22float2(*(__half2*)&dh[ah][n][0]);
                float2 hi = __half22float2(*(__half2*)&dh[ah][n][1]);
                d[ah][n][0] += lo.x; d[ah][n][1] += lo.y;
                d[ah][n][2] += hi.x; d[ah][n][3] += hi.y;
                dh[ah][n][0] = 0u;   dh[ah][n][1] = 0u;
            }
    };
    auto flush_S = [&](int it) {
        #pragma unroll
        for (int r = 0; r < 4; r++) {
            float v = sacc[r];
            v += __shfl_xor_sync(0xffffffffu, v, 8);
            v += __shfl_xor_sync(0xffffffffu, v, 4);
            v += __shfl_xor_sync(0xffffffffu, v, 2);
            v += __shfl_xor_sync(0xffffffffu, v, 1);
            if (q == 0) atomicAdd(&g_S[it * TI + warp * 8 + rh * 4 + r], v);
        }
    };
    auto flush_D = [&](int it) {
        fold();
        #pragma unroll
        for (int ah = 0; ah < 2; ah++) {
            const int r1 = wi * 32 + ah * 16 + (lane >> 2);
            #pragma unroll
            for (int n = 0; n < 4; n++) {
                const int c = wc * 32 + n * 8 + (lane & 3) * 2;
                float* p0 = &g_D[(size_t)(it * TI + r1) * OUT_DIM + c];
                float* p1 = &g_D[(size_t)(it * TI + r1 + 8) * OUT_DIM + c];
                atomicAdd(p0,     d[ah][n][0]);
                atomicAdd(p0 + 1, d[ah][n][1]);
                atomicAdd(p1,     d[ah][n][2]);
                atomicAdd(p1 + 1, d[ah][n][3]);
                d[ah][n][0] = d[ah][n][1] = d[ah][n][2] = d[ah][n][3] = 0.f;
            }
        }
    };
    // half2 P-build: p = adj_h2 * max(G1*F1, G2*F2) (all factors <= 1, fp16-safe)
    auto build_P = [&](int m, uint32_t PB) {
        const __half2 F1a = *(__half2*)&fqr.x, F2a = *(__half2*)&fqr.y;
        const __half2 F1b = *(__half2*)&fqr.z, F2b = *(__half2*)&fqr.w;
        #pragma unroll
        for (int r = 0; r < 4; r++) {
            __half2 e01 = __hmax2(__hmul2(G1b[r], F1a), __hmul2(G2b[r], F2a));
            __half2 e23 = __hmax2(__hmul2(G1b[r], F1b), __hmul2(G2b[r], F2b));
            __half2 p01 = __hmul2(__floats2half2_rn(av[r].x, av[r].y), e01);
            __half2 p23 = __hmul2(__floats2half2_rn(av[r].z, av[r].w), e23);
            __half2 ts = __hadd2(p01, p23);
            sacc[r] += __half2float(__hadd(__low2half(ts), __high2half(ts)));
            asm volatile("st.shared.v2.b32 [%0], {%1, %2};"
                         :: "r"(PB + swz((warp * 8 + rh * 4 + r) * 128 + q * 8)),
                            "r"(*(uint32_t*)&p01), "r"(*(uint32_t*)&p23));
        }
    };

    prefetch(s);
    load_stage(s, 0);
    load_stage(s + 1, 1);
    load_stage(s + 2, 2);
    int it_b = s >> 8;
    load_row_consts(it_b);
    reset_D();
    build_P(s, sb + SM_P);
    prefetch(s + 1);

    for (int mb = s; mb < e; mb += 4) {
        #pragma unroll
        for (int u = 0; u < 4; u++) {
            const int m = mb + u;
            const uint32_t PB = sb + SM_P + (u & 1) * 8192;
            const uint32_t VB = sb + SM_V + u * 16384;

            asm volatile("cp.async.wait_group 2;" ::: "memory");
            __syncthreads();

            load_stage(m + 3, (u + 3) & 3);

            if (m + 1 < e) {
                if (u == 3) {
                    const int it_n = (m + 1) >> 8;
                    if (it_n != it_b) {
                        flush_S(it_b);
                        it_b = it_n;
                        load_row_consts(it_b);
                    }
                }
                build_P(m + 1, sb + SM_P + ((u + 1) & 1) * 8192);
                prefetch(m + 2);
            }

            #pragma unroll
            for (int ks = 0; ks < 4; ks++) {
                uint32_t afr[2][4];
                #pragma unroll
                for (int ah = 0; ah < 2; ah++) {
                    const uint32_t aaddr = PB + swz((wi * 32 + ah * 16 + (lane & 15)) * 128
                                                    + ks * 32 + (lane >> 4) * 16);
                    asm volatile("ldmatrix.sync.aligned.m8n8.x4.shared.b16 {%0,%1,%2,%3},[%4];\n"
                                 : "=r"(afr[ah][0]), "=r"(afr[ah][1]),
                                   "=r"(afr[ah][2]), "=r"(afr[ah][3]) : "r"(aaddr));
                }
                uint32_t bfr[8];
                const int atom = wc >> 1;
                const int cin0 = (wc & 1) * 32 + (lane >> 4) * 8;
                const uint32_t brow = (ks * 16 + (lane & 15)) * 128;
                const uint32_t baddr0 = VB + atom * 8192 + swz(brow + cin0 * 2);
                asm volatile("ldmatrix.sync.aligned.m8n8.x4.trans.shared.b16 {%0,%1,%2,%3},[%4];\n"
                             : "=r"(bfr[0]), "=r"(bfr[1]), "=r"(bfr[2]), "=r"(bfr[3]) : "r"(baddr0));
                const uint32_t baddr1 = VB + atom * 8192 + swz(brow + (cin0 + 16) * 2);
                asm volatile("ldmatrix.sync.aligned.m8n8.x4.trans.shared.b16 {%0,%1,%2,%3},[%4];\n"
                             : "=r"(bfr[4]), "=r"(bfr[5]), "=r"(bfr[6]), "=r"(bfr[7]) : "r"(baddr1));
                #pragma unroll
                for (int ah = 0; ah < 2; ah++)
                    #pragma unroll
                    for (int n = 0; n < 4; n++) {
                        asm volatile(
                            "mma.sync.aligned.m16n8k16.row.col.f16.f16.f16.f16 "
                            "{%0,%1},{%2,%3,%4,%5},{%6,%7},{%0,%1};\n"
                            : "+r"(dh[ah][n][0]), "+r"(dh[ah][n][1])
                            : "r"(afr[ah][0]), "r"(afr[ah][1]), "r"(afr[ah][2]), "r"(afr[ah][3]),
                              "r"(bfr[n * 2]), "r"(bfr[n * 2 + 1]));
                    }
            }

            if (u == 3) {
                if (m + 1 == e || ((m + 1) & (NTJ - 1)) == 0) {
                    flush_D(m >> 8);
                } else {
                    fold();
                }
            }
        }
    }
    flush_S(it_b);
}

// ---------------- K5: normalize + ELU (float4) ----------------
__global__ void k_combine(float* __restrict__ out) {
    const int idx = blockIdx.x * 256 + threadIdx.x;
    const int row = idx >> 5, c4 = idx & 31;
    const float inv = 1.0f / g_S[row];
    float4 v = *(const float4*)&g_D[(size_t)row * OUT_DIM + c4 * 4];
    v.x *= inv; v.y *= inv; v.z *= inv; v.w *= inv;
    float4 o;
    o.x = v.x > 0.f ? v.x : expm1f(v.x);
    o.y = v.y > 0.f ? v.y : expm1f(v.y);
    o.z = v.z > 0.f ? v.z : expm1f(v.z);
    o.w = v.w > 0.f ? v.w : expm1f(v.w);
    *(float4*)&out[(size_t)row * OUT_DIM + c4 * 4] = o;
}

// ---------------- launch ----------------
extern "C" void kernel_launch(void* const* d_in, const int* in_sizes, int n_in,
                              void* d_out, int out_size) {
    const float* inp = (const float*)d_in[0];   // [16384, 256]
    const float* adj = (const float*)d_in[1];   // [8192, 16384]
    const float* W   = (const float*)d_in[2];   // [256, 128]
    const float* a   = (const float*)d_in[3];   // [256, 1]
    float* out = (float*)d_out;                 // [8192, 128]

    cudaFuncSetAttribute(k_attn,   cudaFuncAttributeMaxDynamicSharedMemorySize, SMEM_BYTES);
    cudaFuncSetAttribute(k_gemm1h, cudaFuncAttributeMaxDynamicSharedMemorySize, SMEM_G2);

    k_prep   <<<1024, 256>>>(W);                             // launch 1
    k_gemm1h <<<N_GENES / 128, 256, SMEM_G2>>>(inp, a);      // launch 2
    k_factG  <<<N_REG / 256, 256>>>();                       // launch 3 (packed F/G tables)
    k_attn   <<<GRID_ATTN, 256, SMEM_BYTES>>>(adj);          // launch 4 (ncu target)
    k_combine<<<(N_REG * OUT_DIM / 4) / 256, 256>>>(out);    // launch 5
}